// round 1
// baseline (speedup 1.0000x reference)
#include <cuda_runtime.h>
#include <math.h>
#include <stdint.h>

#define NN 50000
#define EE 800000
#define HIDN 128
#define GG 256

static inline int cdiv_h(int a, int b) { return (a + b - 1) / b; }

// ----------------------------- scratch (device globals) -----------------------------
__device__ float g_x[NN * HIDN];
__device__ float g_Q[NN * HIDN];
__device__ float g_K[NN * HIDN];
__device__ float g_V[NN * HIDN];
__device__ float g_aggr[NN * HIDN];
__device__ float g_h[NN * HIDN];
__device__ float g_mid[NN * 256];
__device__ float g_tDk[32 * HIDN];
__device__ float g_tPk[16 * HIDN];
__device__ float g_tDv[32 * HIDN];
__device__ float g_tPv[16 * HIDN];
__device__ int   g_cnt[NN];
__device__ int   g_segoff[NN + 1];
__device__ int   g_cursor[NN];
__device__ int   g_esorted[EE];
__device__ float g_pool[GG * HIDN];
__device__ int   g_pcnt[GG];

// ----------------------------- helpers -----------------------------
__device__ __forceinline__ float gelu_f(float x) {
    return 0.5f * x * (1.0f + erff(x * 0.7071067811865476f));
}

__device__ __forceinline__ uint32_t f2tf32(float x) {
    uint32_t r;
    asm("cvt.rna.tf32.f32 %0, %1;" : "=r"(r) : "f"(x));
    return r;
}

__device__ __forceinline__ void split_tf32(float x, uint32_t& hi, uint32_t& lo) {
    hi = f2tf32(x);
    lo = f2tf32(x - __uint_as_float(hi));
}

__device__ __forceinline__ void mma_tf32(float c[4], const uint32_t a[4], const uint32_t b[2]) {
    asm volatile(
        "mma.sync.aligned.m16n8k8.row.col.f32.tf32.tf32.f32 "
        "{%0,%1,%2,%3}, {%4,%5,%6,%7}, {%8,%9}, {%0,%1,%2,%3};"
        : "+f"(c[0]), "+f"(c[1]), "+f"(c[2]), "+f"(c[3])
        : "r"(a[0]), "r"(a[1]), "r"(a[2]), "r"(a[3]), "r"(b[0]), "r"(b[1]));
}

// ----------------------------- misc kernels -----------------------------
__global__ void zero_kernel() {
    int i = blockIdx.x * blockDim.x + threadIdx.x;
    if (i < NN) g_cnt[i] = 0;
    if (i < GG * HIDN) g_pool[i] = 0.f;
    if (i < GG) g_pcnt[i] = 0;
}

__global__ void encoder_kernel(const int* __restrict__ attr, const float* __restrict__ aemb) {
    int n = blockIdx.x;
    int c = threadIdx.x;
    int a0 = attr[n * 4 + 0], a1 = attr[n * 4 + 1], a2 = attr[n * 4 + 2], a3 = attr[n * 4 + 3];
    float v = aemb[(0 * 64 + a0) * HIDN + c] + aemb[(1 * 64 + a1) * HIDN + c]
            + aemb[(2 * 64 + a2) * HIDN + c] + aemb[(3 * 64 + a3) * HIDN + c];
    g_x[(size_t)n * HIDN + c] = v;
}

__global__ void count_kernel(const int* __restrict__ tgt) {
    int i = blockIdx.x * blockDim.x + threadIdx.x;
    if (i < EE) atomicAdd(&g_cnt[tgt[i]], 1);
}

__global__ void scan_kernel() {
    const int T = 1024;
    const int CH = (NN + T - 1) / T;
    int t = threadIdx.x;
    int s = t * CH;
    int e = min(s + CH, NN);
    int sum = 0;
    for (int i = s; i < e; i++) sum += g_cnt[i];
    __shared__ int sh[T];
    sh[t] = sum;
    __syncthreads();
    for (int d = 1; d < T; d <<= 1) {
        int v = (t >= d) ? sh[t - d] : 0;
        __syncthreads();
        sh[t] += v;
        __syncthreads();
    }
    int run = (t == 0) ? 0 : sh[t - 1];
    for (int i = s; i < e; i++) {
        g_segoff[i] = run;
        g_cursor[i] = run;
        run += g_cnt[i];
    }
    if (t == 0) g_segoff[NN] = EE;
}

__global__ void scatter_kernel(const int* __restrict__ tgt) {
    int i = blockIdx.x * blockDim.x + threadIdx.x;
    if (i < EE) {
        int tg = tgt[i];
        int pos = atomicAdd(&g_cursor[tg], 1);
        g_esorted[pos] = i;
    }
}

// ----------------------------- GEMM (3xTF32 mma.sync) -----------------------------
enum { EPI_PLAIN = 0, EPI_GELU = 1, EPI_LN = 2 };

template <int KDIM, int NC, int EPI, bool GELU_A>
__global__ void __launch_bounds__(32 * (NC / 32)) gemm_kernel(
    const float* __restrict__ A, const float* __restrict__ B,
    const float* __restrict__ bias, const float* __restrict__ res,
    const float* __restrict__ lng, const float* __restrict__ lnb,
    float* __restrict__ C, int M)
{
    constexpr int TM = 64;
    constexpr int KC = 16;
    constexpr int NWARP = NC / 32;      // 4 or 8
    constexpr int NTHR = 32 * NWARP;
    static_assert(EPI != EPI_LN || NC == 128, "LN epilogue requires NC=128");

    __shared__ float As[TM][KC + 4];
    __shared__ float Bs[KC][NC + 4];

    int tid = threadIdx.x;
    int wid = tid >> 5, lane = tid & 31;
    int g = lane >> 2, q = lane & 3;
    int wrow = (wid & 3) * 16;
    int wcol = (wid >> 2) * 128;
    int r0 = blockIdx.x * TM;

    float acc[16][4];
#pragma unroll
    for (int i = 0; i < 16; i++)
#pragma unroll
        for (int j = 0; j < 4; j++) acc[i][j] = 0.f;

    for (int k0 = 0; k0 < KDIM; k0 += KC) {
        // load A tile [64 x 16]
        for (int j = tid; j < TM * (KC / 4); j += NTHR) {
            int row = j >> 2, c4 = j & 3;
            int gr = r0 + row;
            float4 v = make_float4(0.f, 0.f, 0.f, 0.f);
            if (gr < M) v = *(const float4*)(A + (size_t)gr * KDIM + k0 + c4 * 4);
            if (GELU_A) { v.x = gelu_f(v.x); v.y = gelu_f(v.y); v.z = gelu_f(v.z); v.w = gelu_f(v.w); }
            *(float4*)&As[row][c4 * 4] = v;
        }
        // load B tile [16 x NC]
        for (int j = tid; j < KC * (NC / 4); j += NTHR) {
            int row = j / (NC / 4), c4 = j % (NC / 4);
            *(float4*)&Bs[row][c4 * 4] = *(const float4*)(B + (size_t)(k0 + row) * NC + c4 * 4);
        }
        __syncthreads();
#pragma unroll
        for (int ks = 0; ks < 2; ks++) {
            int kb = ks * 8;
            uint32_t ah[4], al[4];
            split_tf32(As[wrow + g][kb + q],          ah[0], al[0]);
            split_tf32(As[wrow + g + 8][kb + q],      ah[1], al[1]);
            split_tf32(As[wrow + g][kb + q + 4],      ah[2], al[2]);
            split_tf32(As[wrow + g + 8][kb + q + 4],  ah[3], al[3]);
#pragma unroll
            for (int nt = 0; nt < 16; nt++) {
                int n0 = wcol + nt * 8;
                uint32_t bh[2], bl[2];
                split_tf32(Bs[kb + q][n0 + g],     bh[0], bl[0]);
                split_tf32(Bs[kb + 4 + q][n0 + g], bh[1], bl[1]);
                mma_tf32(acc[nt], ah, bh);
                mma_tf32(acc[nt], ah, bl);
                mma_tf32(acc[nt], al, bh);
            }
        }
        __syncthreads();
    }

    int ra = r0 + wrow + g;
    int rb = ra + 8;

    if (EPI == EPI_LN) {
        float sa = 0, qa = 0, sb = 0, qb = 0;
#pragma unroll
        for (int nt = 0; nt < 16; nt++) {
            int col = wcol + nt * 8 + q * 2;
            float b0 = bias ? bias[col] : 0.f;
            float b1 = bias ? bias[col + 1] : 0.f;
            float ra0 = (ra < M) ? res[(size_t)ra * NC + col] : 0.f;
            float ra1 = (ra < M) ? res[(size_t)ra * NC + col + 1] : 0.f;
            float rb0 = (rb < M) ? res[(size_t)rb * NC + col] : 0.f;
            float rb1 = (rb < M) ? res[(size_t)rb * NC + col + 1] : 0.f;
            float va0 = acc[nt][0] + b0 + ra0;
            float va1 = acc[nt][1] + b1 + ra1;
            float vb0 = acc[nt][2] + b0 + rb0;
            float vb1 = acc[nt][3] + b1 + rb1;
            acc[nt][0] = va0; acc[nt][1] = va1; acc[nt][2] = vb0; acc[nt][3] = vb1;
            sa += va0 + va1; qa += va0 * va0 + va1 * va1;
            sb += vb0 + vb1; qb += vb0 * vb0 + vb1 * vb1;
        }
        sa += __shfl_xor_sync(0xffffffffu, sa, 1); sa += __shfl_xor_sync(0xffffffffu, sa, 2);
        qa += __shfl_xor_sync(0xffffffffu, qa, 1); qa += __shfl_xor_sync(0xffffffffu, qa, 2);
        sb += __shfl_xor_sync(0xffffffffu, sb, 1); sb += __shfl_xor_sync(0xffffffffu, sb, 2);
        qb += __shfl_xor_sync(0xffffffffu, qb, 1); qb += __shfl_xor_sync(0xffffffffu, qb, 2);
        float ma = sa * (1.f / 128.f), mb = sb * (1.f / 128.f);
        float rsa = rsqrtf(qa * (1.f / 128.f) - ma * ma + 1e-5f);
        float rsb = rsqrtf(qb * (1.f / 128.f) - mb * mb + 1e-5f);
#pragma unroll
        for (int nt = 0; nt < 16; nt++) {
            int col = wcol + nt * 8 + q * 2;
            float g0 = lng[col], g1 = lng[col + 1], o0 = lnb[col], o1 = lnb[col + 1];
            if (ra < M) {
                float2 st = make_float2((acc[nt][0] - ma) * rsa * g0 + o0,
                                        (acc[nt][1] - ma) * rsa * g1 + o1);
                *(float2*)(C + (size_t)ra * NC + col) = st;
            }
            if (rb < M) {
                float2 st = make_float2((acc[nt][2] - mb) * rsb * g0 + o0,
                                        (acc[nt][3] - mb) * rsb * g1 + o1);
                *(float2*)(C + (size_t)rb * NC + col) = st;
            }
        }
    } else {
#pragma unroll
        for (int nt = 0; nt < 16; nt++) {
            int col = wcol + nt * 8 + q * 2;
            float b0 = bias ? bias[col] : 0.f;
            float b1 = bias ? bias[col + 1] : 0.f;
            float oa0 = acc[nt][0] + b0, oa1 = acc[nt][1] + b1;
            float ob0 = acc[nt][2] + b0, ob1 = acc[nt][3] + b1;
            if (EPI == EPI_GELU) {
                oa0 = gelu_f(oa0); oa1 = gelu_f(oa1);
                ob0 = gelu_f(ob0); ob1 = gelu_f(ob1);
            }
            if (ra < M) *(float2*)(C + (size_t)ra * NC + col) = make_float2(oa0, oa1);
            if (rb < M) *(float2*)(C + (size_t)rb * NC + col) = make_float2(ob0, ob1);
        }
    }
}

// ----------------------------- edge attention (sorted, online softmax) -----------------------------
__global__ void __launch_bounds__(256) edge_attn_kernel(
    const int* __restrict__ esrc, const int* __restrict__ sdist, const int* __restrict__ spath)
{
    int warp = threadIdx.x >> 5, lane = threadIdx.x & 31;
    int n = blockIdx.x * 8 + warp;
    if (n >= NN) return;
    int beg = g_segoff[n], end = g_segoff[n + 1];
    float4 q4 = *(const float4*)(g_Q + (size_t)n * HIDN + lane * 4);
    float m = -INFINITY, den = 0.f;
    float ax = 0.f, ay = 0.f, az = 0.f, aw = 0.f;
    for (int p = beg; p < end; p++) {
        int e = g_esorted[p];
        int s = esrc[e], d = sdist[e], pa = spath[e];
        float4 ks = *(const float4*)(g_K + (size_t)s * HIDN + lane * 4);
        float4 kd = *(const float4*)(g_tDk + d * HIDN + lane * 4);
        float4 kp = *(const float4*)(g_tPk + pa * HIDN + lane * 4);
        float kx = ks.x + kd.x + kp.x;
        float ky = ks.y + kd.y + kp.y;
        float kz = ks.z + kd.z + kp.z;
        float kw = ks.w + kd.w + kp.w;
        float sc = q4.x * kx + q4.y * ky + q4.z * kz + q4.w * kw;
        sc += __shfl_xor_sync(0xffffffffu, sc, 1);
        sc += __shfl_xor_sync(0xffffffffu, sc, 2);
        sc *= 0.25f;  // 1/sqrt(DK=16)
        float4 vs = *(const float4*)(g_V + (size_t)s * HIDN + lane * 4);
        float4 vd = *(const float4*)(g_tDv + d * HIDN + lane * 4);
        float4 vp = *(const float4*)(g_tPv + pa * HIDN + lane * 4);
        float vx = vs.x + vd.x + vp.x;
        float vy = vs.y + vd.y + vp.y;
        float vz = vs.z + vd.z + vp.z;
        float vw = vs.w + vd.w + vp.w;
        float nm = fmaxf(m, sc);
        float f = expf(m - nm);
        float w = expf(sc - nm);
        den = den * f + w;
        ax = ax * f + w * vx;
        ay = ay * f + w * vy;
        az = az * f + w * vz;
        aw = aw * f + w * vw;
        m = nm;
    }
    float inv = 1.f / (den + 1e-16f);
    *(float4*)(g_aggr + (size_t)n * HIDN + lane * 4) =
        make_float4(ax * inv, ay * inv, az * inv, aw * inv);
}

// ----------------------------- pooling + readout -----------------------------
__global__ void pool_kernel(const int* __restrict__ bidx) {
    int n = blockIdx.x;
    int c = threadIdx.x;
    int b = bidx[n];
    atomicAdd(&g_pool[(size_t)b * HIDN + c], g_x[(size_t)n * HIDN + c]);
    if (c == 0) atomicAdd(&g_pcnt[b], 1);
}

__global__ void readout_kernel(const float* __restrict__ Wout, const float* __restrict__ bout,
                               float* __restrict__ out) {
    int gi = blockIdx.x;
    int t = threadIdx.x;
    float c = fmaxf((float)g_pcnt[gi], 1.f);
    float v = g_pool[(size_t)gi * HIDN + t] / c * Wout[t];
    for (int d = 16; d; d >>= 1) v += __shfl_xor_sync(0xffffffffu, v, d);
    __shared__ float sw[4];
    if ((t & 31) == 0) sw[t >> 5] = v;
    __syncthreads();
    if (t == 0) out[gi] = sw[0] + sw[1] + sw[2] + sw[3] + bout[0];
}

// ----------------------------- launch -----------------------------
extern "C" void kernel_launch(void* const* d_in, const int* in_sizes, int n_in,
                              void* d_out, int out_size) {
    const int*   node_attr = (const int*)d_in[0];
    const int*   batch_idx = (const int*)d_in[1];
    const int*   eidx      = (const int*)d_in[2];
    const int*   sdist     = (const int*)d_in[3];
    const int*   spath     = (const int*)d_in[4];
    const float* atom_emb  = (const float*)d_in[5];
    const float* dist_emb  = (const float*)d_in[6];
    const float* path_emb  = (const float*)d_in[7];
    const float* Wq = (const float*)d_in[8];
    const float* bq = (const float*)d_in[9];
    const float* Wk = (const float*)d_in[10];
    const float* bk = (const float*)d_in[11];
    const float* Wv = (const float*)d_in[12];
    const float* bv = (const float*)d_in[13];
    const float* Wa = (const float*)d_in[14];
    const float* ba = (const float*)d_in[15];
    const float* ln1g = (const float*)d_in[16];
    const float* ln1b = (const float*)d_in[17];
    const float* Wmid = (const float*)d_in[18];
    const float* bmid = (const float*)d_in[19];
    const float* Wo = (const float*)d_in[20];
    const float* bo = (const float*)d_in[21];
    const float* ln2g = (const float*)d_in[22];
    const float* ln2b = (const float*)d_in[23];
    const float* Wout = (const float*)d_in[24];
    const float* bout = (const float*)d_in[25];
    float* out = (float*)d_out;

    float *px, *pQ, *pK, *pV, *pag, *ph, *pmid, *pDk, *pPk, *pDv, *pPv;
    cudaGetSymbolAddress((void**)&px, g_x);
    cudaGetSymbolAddress((void**)&pQ, g_Q);
    cudaGetSymbolAddress((void**)&pK, g_K);
    cudaGetSymbolAddress((void**)&pV, g_V);
    cudaGetSymbolAddress((void**)&pag, g_aggr);
    cudaGetSymbolAddress((void**)&ph, g_h);
    cudaGetSymbolAddress((void**)&pmid, g_mid);
    cudaGetSymbolAddress((void**)&pDk, g_tDk);
    cudaGetSymbolAddress((void**)&pPk, g_tPk);
    cudaGetSymbolAddress((void**)&pDv, g_tDv);
    cudaGetSymbolAddress((void**)&pPv, g_tPv);

    const int* esrc = eidx;
    const int* etgt = eidx + EE;
    int gemm_grid = cdiv_h(NN, 64);

    zero_kernel<<<cdiv_h(NN, 256), 256>>>();
    encoder_kernel<<<NN, 128>>>(node_attr, atom_emb);
    count_kernel<<<cdiv_h(EE, 256), 256>>>(etgt);
    scan_kernel<<<1, 1024>>>();
    scatter_kernel<<<cdiv_h(EE, 256), 256>>>(etgt);

    for (int l = 0; l < 2; l++) {
        const float* Wq_l = Wq + (size_t)l * 128 * 128;
        const float* Wk_l = Wk + (size_t)l * 128 * 128;
        const float* Wv_l = Wv + (size_t)l * 128 * 128;
        const float* Wa_l = Wa + (size_t)l * 128 * 128;
        const float* Wm_l = Wmid + (size_t)l * 128 * 256;
        const float* Wo_l = Wo + (size_t)l * 256 * 128;

        // relational tables (fold bk into Dk, bv into Dv)
        gemm_kernel<128, 128, EPI_PLAIN, false><<<1, 128>>>(
            dist_emb + (size_t)l * 32 * 128, Wk_l, bk + l * 128, nullptr, nullptr, nullptr, pDk, 32);
        gemm_kernel<128, 128, EPI_PLAIN, false><<<1, 128>>>(
            path_emb + (size_t)l * 16 * 128, Wk_l, nullptr, nullptr, nullptr, nullptr, pPk, 16);
        gemm_kernel<128, 128, EPI_PLAIN, false><<<1, 128>>>(
            dist_emb + (size_t)l * 32 * 128, Wv_l, bv + l * 128, nullptr, nullptr, nullptr, pDv, 32);
        gemm_kernel<128, 128, EPI_PLAIN, false><<<1, 128>>>(
            path_emb + (size_t)l * 16 * 128, Wv_l, nullptr, nullptr, nullptr, nullptr, pPv, 16);

        // per-node Q/K/V
        gemm_kernel<128, 128, EPI_PLAIN, false><<<gemm_grid, 128>>>(
            px, Wq_l, bq + l * 128, nullptr, nullptr, nullptr, pQ, NN);
        gemm_kernel<128, 128, EPI_PLAIN, false><<<gemm_grid, 128>>>(
            px, Wk_l, nullptr, nullptr, nullptr, nullptr, pK, NN);
        gemm_kernel<128, 128, EPI_PLAIN, false><<<gemm_grid, 128>>>(
            px, Wv_l, nullptr, nullptr, nullptr, nullptr, pV, NN);

        // edge attention -> aggr
        edge_attn_kernel<<<cdiv_h(NN, 8), 256>>>(esrc, sdist, spath);

        // h = LN(gelu(aggr)@Wa + ba + x)
        gemm_kernel<128, 128, EPI_LN, true><<<gemm_grid, 128>>>(
            pag, Wa_l, ba + l * 128, px, ln1g + l * 128, ln1b + l * 128, ph, NN);
        // mid = gelu(h@Wmid + bmid)
        gemm_kernel<128, 256, EPI_GELU, false><<<gemm_grid, 256>>>(
            ph, Wm_l, bmid + l * 256, nullptr, nullptr, nullptr, pmid, NN);
        // x = LN(mid@Wo + bo + h)
        gemm_kernel<256, 128, EPI_LN, false><<<gemm_grid, 128>>>(
            pmid, Wo_l, bo + l * 128, ph, ln2g + l * 128, ln2b + l * 128, px, NN);
    }

    pool_kernel<<<NN, 128>>>(batch_idx);
    readout_kernel<<<GG, 128>>>(Wout, bout, out);
}

// round 2
// speedup vs baseline: 1.3511x; 1.3511x over previous
#include <cuda_runtime.h>
#include <math.h>
#include <stdint.h>

#define NN 50000
#define EE 800000
#define HIDN 128
#define GG 256
#define NBLK 49   // ceil(NN/1024)

static inline int cdiv_h(int a, int b) { return (a + b - 1) / b; }

// ----------------------------- scratch (device globals) -----------------------------
__device__ float g_x[NN * HIDN];
__device__ float g_Q[NN * HIDN];
__device__ float g_K[NN * HIDN];
__device__ float g_V[NN * HIDN];
__device__ float g_aggr[NN * HIDN];
__device__ float g_h[NN * HIDN];
__device__ float g_mid[NN * 256];
__device__ float g_comb[512 * HIDN];
__device__ float g_tDPk[512 * HIDN];
__device__ float g_tDPv[512 * HIDN];
__device__ int   g_cnt[NN];
__device__ int   g_segoff[NN + 1];
__device__ int   g_cursor[NN];
__device__ int   g_srcs[EE];
__device__ int   g_dps[EE];
__device__ int   g_bsum[64];
__device__ int   g_boff[64];
__device__ int   g_gcnt[GG];
__device__ int   g_goff[GG + 1];

// ----------------------------- helpers -----------------------------
__device__ __forceinline__ float gelu_f(float x) {
    return 0.5f * x * (1.0f + erff(x * 0.7071067811865476f));
}

__device__ __forceinline__ uint32_t f2tf32(float x) {
    uint32_t r;
    asm("cvt.rna.tf32.f32 %0, %1;" : "=r"(r) : "f"(x));
    return r;
}

__device__ __forceinline__ void split_tf32(float x, uint32_t& hi, uint32_t& lo) {
    hi = f2tf32(x);
    lo = f2tf32(x - __uint_as_float(hi));
}

__device__ __forceinline__ void mma_tf32(float c[4], const uint32_t a[4], const uint32_t b[2]) {
    asm volatile(
        "mma.sync.aligned.m16n8k8.row.col.f32.tf32.tf32.f32 "
        "{%0,%1,%2,%3}, {%4,%5,%6,%7}, {%8,%9}, {%0,%1,%2,%3};"
        : "+f"(c[0]), "+f"(c[1]), "+f"(c[2]), "+f"(c[3])
        : "r"(a[0]), "r"(a[1]), "r"(a[2]), "r"(a[3]), "r"(b[0]), "r"(b[1]));
}

// ----------------------------- misc kernels -----------------------------
__global__ void zero_kernel() {
    int i = blockIdx.x * blockDim.x + threadIdx.x;
    if (i < NN) g_cnt[i] = 0;
    if (i < GG) g_gcnt[i] = 0;
}

__global__ void encoder_kernel(const int* __restrict__ attr, const float* __restrict__ aemb) {
    int c = threadIdx.x;
    for (int n = blockIdx.x; n < NN; n += gridDim.x) {
        int a0 = attr[n * 4 + 0], a1 = attr[n * 4 + 1], a2 = attr[n * 4 + 2], a3 = attr[n * 4 + 3];
        float v = aemb[(0 * 64 + a0) * HIDN + c] + aemb[(1 * 64 + a1) * HIDN + c]
                + aemb[(2 * 64 + a2) * HIDN + c] + aemb[(3 * 64 + a3) * HIDN + c];
        g_x[(size_t)n * HIDN + c] = v;
    }
}

__global__ void count_kernel(const int* __restrict__ tgt, const int* __restrict__ bidx) {
    int i = blockIdx.x * blockDim.x + threadIdx.x;
    if (i < EE) atomicAdd(&g_cnt[tgt[i]], 1);
    if (i < NN) atomicAdd(&g_gcnt[bidx[i]], 1);
}

// stage 1: per-block (1024 elems) exclusive prefix + block sums
__global__ void scan1_kernel() {
    __shared__ int sh[256];
    int blk = blockIdx.x, t = threadIdx.x;
    int idx4 = blk * 256 + t;
    int4 v4 = make_int4(0, 0, 0, 0);
    if (idx4 < NN / 4) v4 = ((const int4*)g_cnt)[idx4];
    int s = v4.x + v4.y + v4.z + v4.w;
    sh[t] = s;
    __syncthreads();
    for (int d = 1; d < 256; d <<= 1) {
        int v = (t >= d) ? sh[t - d] : 0;
        __syncthreads();
        sh[t] += v;
        __syncthreads();
    }
    int run = (t == 0) ? 0 : sh[t - 1];
    int base = blk * 1024 + t * 4;
    int vv[4] = {v4.x, v4.y, v4.z, v4.w};
    for (int j = 0; j < 4; j++) {
        if (base + j < NN) g_segoff[base + j] = run;
        run += vv[j];
    }
    if (t == 255) g_bsum[blk] = sh[255];
}

// stage 2: scan block sums (49) + scan graph counts (256)
__global__ void scan2_kernel() {
    __shared__ int sg[256];
    __shared__ int sb[64];
    int t = threadIdx.x;
    sg[t] = g_gcnt[t];
    if (t < 64) sb[t] = (t < NBLK) ? g_bsum[t] : 0;
    __syncthreads();
    for (int d = 1; d < 256; d <<= 1) {
        int v = (t >= d) ? sg[t - d] : 0;
        int v2 = 0;
        if (t < 64 && t >= d && d < 64) v2 = sb[t - d];
        __syncthreads();
        sg[t] += v;
        if (t < 64 && d < 64) sb[t] += v2;
        __syncthreads();
    }
    g_goff[t + 1] = sg[t];
    if (t == 0) g_goff[0] = 0;
    if (t < 64) g_boff[t] = (t == 0) ? 0 : sb[t - 1];
}

// stage 3: add block offsets, init cursors
__global__ void scan3_kernel() {
    int blk = blockIdx.x, t = threadIdx.x;
    int off = g_boff[blk];
    int base = blk * 1024 + t * 4;
    for (int j = 0; j < 4; j++) {
        int i = base + j;
        if (i < NN) {
            int v = g_segoff[i] + off;
            g_segoff[i] = v;
            g_cursor[i] = v;
        }
    }
    if (blk == 0 && t == 0) g_segoff[NN] = EE;
}

__global__ void scatter_kernel(const int* __restrict__ src, const int* __restrict__ tgt,
                               const int* __restrict__ sdist, const int* __restrict__ spath) {
    int i = blockIdx.x * blockDim.x + threadIdx.x;
    if (i < EE) {
        int tg = tgt[i];
        int pos = atomicAdd(&g_cursor[tg], 1);
        g_srcs[pos] = src[i];
        g_dps[pos] = (sdist[i] << 4) | spath[i];
    }
}

// combine dist+path embeddings into one 512-row matrix
__global__ void comb_kernel(const float* __restrict__ de, const float* __restrict__ pe) {
    int c = threadIdx.x;
    for (int r = blockIdx.x; r < 512; r += gridDim.x) {
        int d = r >> 4, p = r & 15;
        g_comb[r * HIDN + c] = de[d * HIDN + c] + pe[p * HIDN + c];
    }
}

// ----------------------------- GEMM (3xTF32, pre-split hi/lo in smem) -----------------------------
enum { EPI_PLAIN = 0, EPI_GELU = 1, EPI_LN = 2 };

template <int KDIM, int NC, int EPI, bool GELU_A>
__global__ void __launch_bounds__(256) gemm2_kernel(
    const float* __restrict__ A, const float* __restrict__ B,
    const float* __restrict__ bias, const float* __restrict__ res,
    const float* __restrict__ lng, const float* __restrict__ lnb,
    float* __restrict__ C, int M)
{
    constexpr int TM = (NC == 128) ? 128 : 64;
    constexpr int KC = 16;
    constexpr int APAD = 4;  // row stride 20 float2 = 160B (16B aligned)
    constexpr int BPAD = 4;
    static_assert(EPI != EPI_LN || NC == 128, "LN epilogue requires NC=128");

    __shared__ float2 As[TM][KC + APAD];
    __shared__ float2 Bs[KC][NC + BPAD];

    constexpr int AL = TM * KC / (4 * 256);  // float4 loads per thread
    constexpr int BL = KC * NC / (4 * 256);

    int tid = threadIdx.x;
    int wid = tid >> 5, lane = tid & 31;
    int g = lane >> 2, q = lane & 3;
    int wrow = (NC == 128) ? wid * 16 : (wid & 3) * 16;
    int wcol = (NC == 128) ? 0 : (wid >> 2) * 128;
    int r0 = blockIdx.x * TM;

    float acc[16][4];
#pragma unroll
    for (int i = 0; i < 16; i++)
#pragma unroll
        for (int j = 0; j < 4; j++) acc[i][j] = 0.f;

    float4 aS[AL], bS[BL];

    // prologue: stage chunk 0
#pragma unroll
    for (int i = 0; i < AL; i++) {
        int j = tid + i * 256;
        int row = j >> 2, c4 = j & 3;
        int gr = r0 + row;
        aS[i] = (gr < M) ? *(const float4*)(A + (size_t)gr * KDIM + c4 * 4)
                         : make_float4(0.f, 0.f, 0.f, 0.f);
    }
#pragma unroll
    for (int i = 0; i < BL; i++) {
        int j = tid + i * 256;
        int row = j / (NC / 4), c = j % (NC / 4);
        bS[i] = *(const float4*)(B + (size_t)row * NC + c * 4);
    }

    for (int k0 = 0; k0 < KDIM; k0 += KC) {
        // store staged -> smem with hi/lo split (convert once per element)
#pragma unroll
        for (int i = 0; i < AL; i++) {
            int j = tid + i * 256;
            int row = j >> 2, c4 = j & 3;
            float4 v = aS[i];
            if (GELU_A) { v.x = gelu_f(v.x); v.y = gelu_f(v.y); v.z = gelu_f(v.z); v.w = gelu_f(v.w); }
            float2* dst = &As[row][c4 * 4];
            uint32_t h, l;
            split_tf32(v.x, h, l); dst[0] = make_float2(__uint_as_float(h), __uint_as_float(l));
            split_tf32(v.y, h, l); dst[1] = make_float2(__uint_as_float(h), __uint_as_float(l));
            split_tf32(v.z, h, l); dst[2] = make_float2(__uint_as_float(h), __uint_as_float(l));
            split_tf32(v.w, h, l); dst[3] = make_float2(__uint_as_float(h), __uint_as_float(l));
        }
#pragma unroll
        for (int i = 0; i < BL; i++) {
            int j = tid + i * 256;
            int row = j / (NC / 4), c = j % (NC / 4);
            float4 v = bS[i];
            float2* dst = &Bs[row][c * 4];
            uint32_t h, l;
            split_tf32(v.x, h, l); dst[0] = make_float2(__uint_as_float(h), __uint_as_float(l));
            split_tf32(v.y, h, l); dst[1] = make_float2(__uint_as_float(h), __uint_as_float(l));
            split_tf32(v.z, h, l); dst[2] = make_float2(__uint_as_float(h), __uint_as_float(l));
            split_tf32(v.w, h, l); dst[3] = make_float2(__uint_as_float(h), __uint_as_float(l));
        }
        __syncthreads();

        // prefetch next chunk while doing mma on this one
        int kn = k0 + KC;
        if (kn < KDIM) {
#pragma unroll
            for (int i = 0; i < AL; i++) {
                int j = tid + i * 256;
                int row = j >> 2, c4 = j & 3;
                int gr = r0 + row;
                aS[i] = (gr < M) ? *(const float4*)(A + (size_t)gr * KDIM + kn + c4 * 4)
                                 : make_float4(0.f, 0.f, 0.f, 0.f);
            }
#pragma unroll
            for (int i = 0; i < BL; i++) {
                int j = tid + i * 256;
                int row = j / (NC / 4), c = j % (NC / 4);
                bS[i] = *(const float4*)(B + (size_t)(kn + row) * NC + c * 4);
            }
        }

#pragma unroll
        for (int ks = 0; ks < 2; ks++) {
            int kb = ks * 8;
            float2 t0 = As[wrow + g][kb + q];
            float2 t1 = As[wrow + g + 8][kb + q];
            float2 t2 = As[wrow + g][kb + q + 4];
            float2 t3 = As[wrow + g + 8][kb + q + 4];
            uint32_t ah[4] = {__float_as_uint(t0.x), __float_as_uint(t1.x),
                              __float_as_uint(t2.x), __float_as_uint(t3.x)};
            uint32_t al[4] = {__float_as_uint(t0.y), __float_as_uint(t1.y),
                              __float_as_uint(t2.y), __float_as_uint(t3.y)};
#pragma unroll
            for (int nt = 0; nt < 16; nt++) {
                int n0 = wcol + nt * 8;
                float2 b0 = Bs[kb + q][n0 + g];
                float2 b1 = Bs[kb + 4 + q][n0 + g];
                uint32_t bh[2] = {__float_as_uint(b0.x), __float_as_uint(b1.x)};
                uint32_t bl[2] = {__float_as_uint(b0.y), __float_as_uint(b1.y)};
                mma_tf32(acc[nt], ah, bh);
                mma_tf32(acc[nt], ah, bl);
                mma_tf32(acc[nt], al, bh);
            }
        }
        __syncthreads();
    }

    int ra = r0 + wrow + g;
    int rb = ra + 8;

    if (EPI == EPI_LN) {
        float sa = 0, qa = 0, sb = 0, qb = 0;
#pragma unroll
        for (int nt = 0; nt < 16; nt++) {
            int col = wcol + nt * 8 + q * 2;
            float b0 = bias[col];
            float b1 = bias[col + 1];
            float ra0 = (ra < M) ? res[(size_t)ra * NC + col] : 0.f;
            float ra1 = (ra < M) ? res[(size_t)ra * NC + col + 1] : 0.f;
            float rb0 = (rb < M) ? res[(size_t)rb * NC + col] : 0.f;
            float rb1 = (rb < M) ? res[(size_t)rb * NC + col + 1] : 0.f;
            float va0 = acc[nt][0] + b0 + ra0;
            float va1 = acc[nt][1] + b1 + ra1;
            float vb0 = acc[nt][2] + b0 + rb0;
            float vb1 = acc[nt][3] + b1 + rb1;
            acc[nt][0] = va0; acc[nt][1] = va1; acc[nt][2] = vb0; acc[nt][3] = vb1;
            sa += va0 + va1; qa += va0 * va0 + va1 * va1;
            sb += vb0 + vb1; qb += vb0 * vb0 + vb1 * vb1;
        }
        sa += __shfl_xor_sync(0xffffffffu, sa, 1); sa += __shfl_xor_sync(0xffffffffu, sa, 2);
        qa += __shfl_xor_sync(0xffffffffu, qa, 1); qa += __shfl_xor_sync(0xffffffffu, qa, 2);
        sb += __shfl_xor_sync(0xffffffffu, sb, 1); sb += __shfl_xor_sync(0xffffffffu, sb, 2);
        qb += __shfl_xor_sync(0xffffffffu, qb, 1); qb += __shfl_xor_sync(0xffffffffu, qb, 2);
        float ma = sa * (1.f / 128.f), mb = sb * (1.f / 128.f);
        float rsa = rsqrtf(qa * (1.f / 128.f) - ma * ma + 1e-5f);
        float rsb = rsqrtf(qb * (1.f / 128.f) - mb * mb + 1e-5f);
#pragma unroll
        for (int nt = 0; nt < 16; nt++) {
            int col = wcol + nt * 8 + q * 2;
            float g0 = lng[col], g1 = lng[col + 1], o0 = lnb[col], o1 = lnb[col + 1];
            if (ra < M) {
                *(float2*)(C + (size_t)ra * NC + col) =
                    make_float2((acc[nt][0] - ma) * rsa * g0 + o0,
                                (acc[nt][1] - ma) * rsa * g1 + o1);
            }
            if (rb < M) {
                *(float2*)(C + (size_t)rb * NC + col) =
                    make_float2((acc[nt][2] - mb) * rsb * g0 + o0,
                                (acc[nt][3] - mb) * rsb * g1 + o1);
            }
        }
    } else {
#pragma unroll
        for (int nt = 0; nt < 16; nt++) {
            int col = wcol + nt * 8 + q * 2;
            float b0 = bias ? bias[col] : 0.f;
            float b1 = bias ? bias[col + 1] : 0.f;
            float oa0 = acc[nt][0] + b0, oa1 = acc[nt][1] + b1;
            float ob0 = acc[nt][2] + b0, ob1 = acc[nt][3] + b1;
            if (EPI == EPI_GELU) {
                oa0 = gelu_f(oa0); oa1 = gelu_f(oa1);
                ob0 = gelu_f(ob0); ob1 = gelu_f(ob1);
            }
            if (ra < M) *(float2*)(C + (size_t)ra * NC + col) = make_float2(oa0, oa1);
            if (rb < M) *(float2*)(C + (size_t)rb * NC + col) = make_float2(ob0, ob1);
        }
    }
}

// ----------------------------- edge attention (sorted, no-max softmax) -----------------------------
__global__ void __launch_bounds__(256) edge_attn_kernel() {
    int warp = threadIdx.x >> 5, lane = threadIdx.x & 31;
    int n = blockIdx.x * 8 + warp;
    if (n >= NN) return;
    int beg = g_segoff[n], end = g_segoff[n + 1];
    float4 q4 = *(const float4*)(g_Q + (size_t)n * HIDN + lane * 4);
    float den = 0.f, ax = 0.f, ay = 0.f, az = 0.f, aw = 0.f;
#pragma unroll 2
    for (int p = beg; p < end; p++) {
        int s = g_srcs[p];
        int idx = g_dps[p];
        float4 ks = *(const float4*)(g_K + (size_t)s * HIDN + lane * 4);
        float4 kt = *(const float4*)(g_tDPk + (size_t)idx * HIDN + lane * 4);
        float sc = q4.x * (ks.x + kt.x) + q4.y * (ks.y + kt.y)
                 + q4.z * (ks.z + kt.z) + q4.w * (ks.w + kt.w);
        sc += __shfl_xor_sync(0xffffffffu, sc, 1);
        sc += __shfl_xor_sync(0xffffffffu, sc, 2);
        float w = __expf(sc * 0.25f);  // 1/sqrt(DK=16); scores are small post-LN, no max needed
        float4 vs = *(const float4*)(g_V + (size_t)s * HIDN + lane * 4);
        float4 vt = *(const float4*)(g_tDPv + (size_t)idx * HIDN + lane * 4);
        den += w;
        ax += w * (vs.x + vt.x);
        ay += w * (vs.y + vt.y);
        az += w * (vs.z + vt.z);
        aw += w * (vs.w + vt.w);
    }
    float inv = 1.f / (den + 1e-16f);
    *(float4*)(g_aggr + (size_t)n * HIDN + lane * 4) =
        make_float4(ax * inv, ay * inv, az * inv, aw * inv);
}

// ----------------------------- fused pool + readout -----------------------------
__global__ void pool_readout_kernel(const float* __restrict__ Wout, const float* __restrict__ bout,
                                    float* __restrict__ out) {
    int gi = blockIdx.x;
    int t = threadIdx.x;  // 128
    int s = g_goff[gi], e = g_goff[gi + 1];
    float acc = 0.f;
    for (int n = s; n < e; n++) acc += g_x[(size_t)n * HIDN + t];
    float cnt = fmaxf((float)(e - s), 1.f);
    float v = acc / cnt * Wout[t];
    for (int d = 16; d; d >>= 1) v += __shfl_xor_sync(0xffffffffu, v, d);
    __shared__ float sw[4];
    if ((t & 31) == 0) sw[t >> 5] = v;
    __syncthreads();
    if (t == 0) out[gi] = sw[0] + sw[1] + sw[2] + sw[3] + bout[0];
}

// ----------------------------- launch -----------------------------
extern "C" void kernel_launch(void* const* d_in, const int* in_sizes, int n_in,
                              void* d_out, int out_size) {
    const int*   node_attr = (const int*)d_in[0];
    const int*   batch_idx = (const int*)d_in[1];
    const int*   eidx      = (const int*)d_in[2];
    const int*   sdist     = (const int*)d_in[3];
    const int*   spath     = (const int*)d_in[4];
    const float* atom_emb  = (const float*)d_in[5];
    const float* dist_emb  = (const float*)d_in[6];
    const float* path_emb  = (const float*)d_in[7];
    const float* Wq = (const float*)d_in[8];
    const float* bq = (const float*)d_in[9];
    const float* Wk = (const float*)d_in[10];
    const float* bk = (const float*)d_in[11];
    const float* Wv = (const float*)d_in[12];
    const float* bv = (const float*)d_in[13];
    const float* Wa = (const float*)d_in[14];
    const float* ba = (const float*)d_in[15];
    const float* ln1g = (const float*)d_in[16];
    const float* ln1b = (const float*)d_in[17];
    const float* Wmid = (const float*)d_in[18];
    const float* bmid = (const float*)d_in[19];
    const float* Wo = (const float*)d_in[20];
    const float* bo = (const float*)d_in[21];
    const float* ln2g = (const float*)d_in[22];
    const float* ln2b = (const float*)d_in[23];
    const float* Wout = (const float*)d_in[24];
    const float* bout = (const float*)d_in[25];
    float* out = (float*)d_out;

    float *px, *pQ, *pK, *pV, *pag, *ph, *pmid, *pcomb, *pDPk, *pDPv;
    cudaGetSymbolAddress((void**)&px, g_x);
    cudaGetSymbolAddress((void**)&pQ, g_Q);
    cudaGetSymbolAddress((void**)&pK, g_K);
    cudaGetSymbolAddress((void**)&pV, g_V);
    cudaGetSymbolAddress((void**)&pag, g_aggr);
    cudaGetSymbolAddress((void**)&ph, g_h);
    cudaGetSymbolAddress((void**)&pmid, g_mid);
    cudaGetSymbolAddress((void**)&pcomb, g_comb);
    cudaGetSymbolAddress((void**)&pDPk, g_tDPk);
    cudaGetSymbolAddress((void**)&pDPv, g_tDPv);

    const int* esrc = eidx;
    const int* etgt = eidx + EE;
    int grid128 = cdiv_h(NN, 128);  // TM=128
    int grid64  = cdiv_h(NN, 64);   // TM=64 (NC=256)

    zero_kernel<<<cdiv_h(NN, 256), 256>>>();
    encoder_kernel<<<512, 128>>>(node_attr, atom_emb);
    count_kernel<<<cdiv_h(EE, 256), 256>>>(etgt, batch_idx);
    scan1_kernel<<<NBLK, 256>>>();
    scan2_kernel<<<1, 256>>>();
    scan3_kernel<<<NBLK, 256>>>();
    scatter_kernel<<<cdiv_h(EE, 256), 256>>>(esrc, etgt, sdist, spath);

    for (int l = 0; l < 2; l++) {
        const float* Wq_l = Wq + (size_t)l * 128 * 128;
        const float* Wk_l = Wk + (size_t)l * 128 * 128;
        const float* Wv_l = Wv + (size_t)l * 128 * 128;
        const float* Wa_l = Wa + (size_t)l * 128 * 128;
        const float* Wm_l = Wmid + (size_t)l * 128 * 256;
        const float* Wo_l = Wo + (size_t)l * 256 * 128;

        // combined relational tables: (dist_emb[d] + path_emb[p]) @ W + b
        comb_kernel<<<128, 128>>>(dist_emb + (size_t)l * 32 * 128,
                                  path_emb + (size_t)l * 16 * 128);
        gemm2_kernel<128, 128, EPI_PLAIN, false><<<4, 256>>>(
            pcomb, Wk_l, bk + l * 128, nullptr, nullptr, nullptr, pDPk, 512);
        gemm2_kernel<128, 128, EPI_PLAIN, false><<<4, 256>>>(
            pcomb, Wv_l, bv + l * 128, nullptr, nullptr, nullptr, pDPv, 512);

        // per-node Q/K/V
        gemm2_kernel<128, 128, EPI_PLAIN, false><<<grid128, 256>>>(
            px, Wq_l, bq + l * 128, nullptr, nullptr, nullptr, pQ, NN);
        gemm2_kernel<128, 128, EPI_PLAIN, false><<<grid128, 256>>>(
            px, Wk_l, nullptr, nullptr, nullptr, nullptr, pK, NN);
        gemm2_kernel<128, 128, EPI_PLAIN, false><<<grid128, 256>>>(
            px, Wv_l, nullptr, nullptr, nullptr, nullptr, pV, NN);

        // edge attention -> aggr
        edge_attn_kernel<<<cdiv_h(NN, 8), 256>>>();

        // h = LN(gelu(aggr)@Wa + ba + x)
        gemm2_kernel<128, 128, EPI_LN, true><<<grid128, 256>>>(
            pag, Wa_l, ba + l * 128, px, ln1g + l * 128, ln1b + l * 128, ph, NN);
        // mid = gelu(h@Wmid + bmid)
        gemm2_kernel<128, 256, EPI_GELU, false><<<grid64, 256>>>(
            ph, Wm_l, bmid + l * 256, nullptr, nullptr, nullptr, pmid, NN);
        // x = LN(mid@Wo + bo + h)
        gemm2_kernel<256, 128, EPI_LN, false><<<grid128, 256>>>(
            pmid, Wo_l, bo + l * 128, ph, ln2g + l * 128, ln2b + l * 128, px, NN);
    }

    pool_readout_kernel<<<GG, 128>>>(Wout, bout, out);
}